// round 6
// baseline (speedup 1.0000x reference)
#include <cuda_runtime.h>
#include <cuda_bf16.h>
#include <cstdint>

#define CIN   256
#define COUT  256
#define LEN   8192
#define KK    7
#define BATCH 4
#define NT    128    // l-tile of main kernel
#define TLO   128    // l-tile of offsets kernel
#define NCHUNK 4     // i-chunks of 64 per k

// ---------------- device scratch ----------------
__device__ int2          g_tidx[BATCH * KK * LEN];   // (x0c, x1c)
__device__ float2        g_tw[BATCH * KK * LEN];     // (wa, wb)
// weight tiles: t = ((k*4+ic)*2+oh)*2+plane, each [128 o][64 i] bf16, SW128 pre-swizzled
__device__ __nv_bfloat16 g_wA[KK * NCHUNK * 2 * 2 * 8192];

#define SWZ128(x)  ((x) ^ (((x) >> 3) & 0x70))

// ---------------- PTX helpers (portable, sm_80-era) ----------------
__device__ __forceinline__ uint32_t smem_u32(const void* p) {
    uint32_t a;
    asm("{ .reg .u64 t; cvta.to.shared.u64 t, %1; cvt.u32.u64 %0, t; }" : "=r"(a) : "l"(p));
    return a;
}
__device__ __forceinline__ void cp16(uint32_t dst, const void* src) {
    asm volatile("cp.async.cg.shared.global [%0], [%1], 16;" :: "r"(dst), "l"(src));
}
__device__ __forceinline__ void ldsm4(uint32_t* r, uint32_t addr) {
    asm volatile("ldmatrix.sync.aligned.m8n8.x4.shared.b16 {%0,%1,%2,%3}, [%4];"
        : "=r"(r[0]), "=r"(r[1]), "=r"(r[2]), "=r"(r[3]) : "r"(addr));
}
__device__ __forceinline__ void mma16816(float* c, const uint32_t* a, const uint32_t* b) {
    asm volatile("mma.sync.aligned.m16n8k16.row.col.f32.bf16.bf16.f32 "
        "{%0,%1,%2,%3}, {%4,%5,%6,%7}, {%8,%9}, {%0,%1,%2,%3};"
        : "+f"(c[0]), "+f"(c[1]), "+f"(c[2]), "+f"(c[3])
        : "r"(a[0]), "r"(a[1]), "r"(a[2]), "r"(a[3]), "r"(b[0]), "r"(b[1]));
}

// ---------- kernel 1: weight split + pre-swizzle ----------
__global__ void wprep_kernel(const float* __restrict__ w) {
    int e = blockIdx.x * 256 + threadIdx.x;
    if (e >= KK * NCHUNK * 2 * 2 * 8192) return;
    int t  = e >> 13;
    int r  = e & 8191;
    int o  = r >> 6;
    int i  = r & 63;
    int plane = t & 1;
    int oh    = (t >> 1) & 1;
    int ic    = (t >> 2) & 3;
    int k     = t >> 4;
    float v = w[((oh * 128 + o) * CIN + ic * 64 + i) * KK + k];
    __nv_bfloat16 hi  = __float2bfloat16(v);
    __nv_bfloat16 val = plane ? __float2bfloat16(v - __bfloat162float(hi)) : hi;
    uint32_t swz = SWZ128((uint32_t)(o * 128 + i * 2));
    g_wA[t * 8192 + (swz >> 1)] = val;
}

// ---------- kernel 2: offset conv + interpolation tables ----------
__global__ __launch_bounds__(256, 1) void offsets_kernel(
    const float* __restrict__ x,
    const float* __restrict__ ow,
    const float* __restrict__ ob)
{
    extern __shared__ float sm[];
    float* xs  = sm;              // 256 * 136
    float* ows = sm + 256 * 136;  // 7 * 256 * 8

    int tid = threadIdx.x;
    int b   = blockIdx.y;
    int l0  = blockIdx.x * TLO;
    const float* xb = x + (size_t)b * CIN * LEN;

    for (int idx = tid; idx < 256 * 134; idx += 256) {
        int i = idx / 134;
        int c = idx - i * 134;
        int g = l0 - 3 + c;
        xs[i * 136 + c] = (g >= 0 && g < LEN) ? xb[i * LEN + g] : 0.0f;
    }
    for (int e = tid; e < KK * CIN * KK; e += 256) {
        int r  = e / 7;
        int kk = e - r * 7;
        ows[r * 8 + kk] = ow[e];
    }
    __syncthreads();

    int w    = tid >> 5;
    int lane = tid & 31;
    if (w < 7) {
        int k = w;
        float a0 = 0.f, a1 = 0.f, a2 = 0.f, a3 = 0.f;
        const float* xrow0 = xs + 4 * lane;
        const float* wrow  = ows + k * 256 * 8;
        #pragma unroll 4
        for (int i = 0; i < 256; i++) {
            const float4* xr = (const float4*)(xrow0 + i * 136);
            float4 A = xr[0], B4 = xr[1], C4 = xr[2];
            float xw[12] = {A.x, A.y, A.z, A.w, B4.x, B4.y, B4.z, B4.w,
                            C4.x, C4.y, C4.z, C4.w};
            const float4* wr = (const float4*)(wrow + i * 8);
            float4 W0 = wr[0], W1 = wr[1];
            float wv[7] = {W0.x, W0.y, W0.z, W0.w, W1.x, W1.y, W1.z};
            #pragma unroll
            for (int kk = 0; kk < 7; kk++) {
                a0 += wv[kk] * xw[0 + kk];
                a1 += wv[kk] * xw[1 + kk];
                a2 += wv[kk] * xw[2 + kk];
                a3 += wv[kk] * xw[3 + kk];
            }
        }
        float bk = ob[k];
        float accs[4] = {a0, a1, a2, a3};
        #pragma unroll
        for (int d = 0; d < 4; d++) {
            int lg = l0 + 4 * lane + d;
            float loc = (float)(lg + k) + accs[d] + bk;
            int ix0 = (int)floorf(loc);
            int i0c = min(max(ix0, 0), LEN - 1);
            int i1c = min(max(ix0 + 1, 0), LEN - 1);
            int o = (b * 7 + k) * LEN + lg;
            g_tidx[o] = make_int2(i0c, i1c);
            g_tw[o]   = make_float2((float)i1c - loc, loc - (float)i0c);
        }
    }
}

// ---------- kernel 3: main GEMM via ldmatrix + mma.sync (bf16 split x3) ----------
// CTA: (ltile 128, ohalf 128, b). 8 warps = 2(o) x 4(l). Warp tile 64o x 32l.
// Loop order: ic OUTER, k INNER -> gather addresses for consecutive k differ by ~1
// element, so k>0 gathers hit L1 (slab ~36KB stays resident).
__global__ __launch_bounds__(256, 2) void main_kernel(
    const float* __restrict__ x,
    const float* __restrict__ bias,
    float* __restrict__ out)
{
    extern __shared__ char smem[];
    uint32_t sb  = smem_u32(smem);
    uint32_t aHI = sb;
    uint32_t aLO = sb + 16384;
    uint32_t bHI = sb + 32768;
    uint32_t bLO = sb + 49152;

    int tid  = threadIdx.x;
    int wid  = tid >> 5;
    int lane = tid & 31;
    int l0   = blockIdx.x * NT;
    int oh   = blockIdx.y;
    int b    = blockIdx.z;
    int ow   = wid >> 2;     // 0..1 -> 64-o subtile
    int lw   = wid & 3;      // 0..3 -> 32-l subtile
    const float* xb = x + (size_t)b * CIN * LEN;

    float c[4][4][4];
    #pragma unroll
    for (int ot = 0; ot < 4; ot++)
        #pragma unroll
        for (int nt = 0; nt < 4; nt++)
            #pragma unroll
            for (int r = 0; r < 4; r++) c[ot][nt][r] = 0.f;

    // staging thread role: l-row and i-half
    int sl = tid >> 1;
    int ih = (tid & 1) * 32;

    for (int ic = 0; ic < NCHUNK; ic++) {
        for (int k = 0; k < KK; k++) {
            // per-(l,k) interpolation params
            int tix = (b * 7 + k) * LEN + l0 + sl;
            int2   ii = g_tidx[tix];
            float2 wv = g_tw[tix];
            const float* p0 = xb + ii.x;
            const float* p1 = xb + ii.y;

            // ---- A tiles via cp.async (overlaps B gather below) ----
            {
                int tb = ((k * NCHUNK + ic) * 2 + oh) * 2;
                const char* srcH = (const char*)(g_wA + (size_t)tb * 8192);
                const char* srcL = srcH + 16384;
                #pragma unroll
                for (int q = 0; q < 4; q++) {
                    cp16(aHI + q * 4096 + tid * 16, srcH + q * 4096 + tid * 16);
                    cp16(aLO + q * 4096 + tid * 16, srcL + q * 4096 + tid * 16);
                }
                asm volatile("cp.async.commit_group;" ::: "memory");
            }
            // ---- B tile: gather + interp + hi/lo split -> SW128 smem ----
            {
                int ibase = ic * 64 + ih;
                #pragma unroll
                for (int g = 0; g < 4; g++) {
                    uint32_t hp[4], lp[4];
                    #pragma unroll
                    for (int j = 0; j < 4; j++) {
                        size_t i0 = (size_t)(ibase + g * 8 + j * 2) * LEN;
                        float v0 = wv.x * p0[i0]       + wv.y * p1[i0];
                        float v1 = wv.x * p0[i0 + LEN] + wv.y * p1[i0 + LEN];
                        __nv_bfloat16 h0 = __float2bfloat16(v0);
                        __nv_bfloat16 h1 = __float2bfloat16(v1);
                        __nv_bfloat16 e0 = __float2bfloat16(v0 - __bfloat162float(h0));
                        __nv_bfloat16 e1 = __float2bfloat16(v1 - __bfloat162float(h1));
                        __nv_bfloat162 hh(h0, h1), ll(e0, e1);
                        hp[j] = *(uint32_t*)&hh;
                        lp[j] = *(uint32_t*)&ll;
                    }
                    uint32_t so = SWZ128((uint32_t)(sl * 128 + (ih + g * 8) * 2));
                    *(uint4*)(smem + 32768 + so) = make_uint4(hp[0], hp[1], hp[2], hp[3]);
                    *(uint4*)(smem + 49152 + so) = make_uint4(lp[0], lp[1], lp[2], lp[3]);
                }
            }
            asm volatile("cp.async.wait_group 0;" ::: "memory");
            __syncthreads();

            // ---- mma phase: 4 k-steps of 16 i ----
            #pragma unroll
            for (int ks = 0; ks < 4; ks++) {
                uint32_t bh[4][2], bl[4][2];
                #pragma unroll
                for (int np = 0; np < 2; np++) {
                    // non-trans B load: m0=(ntile 2np, k-lo), m1=(ntile 2np, k-hi),
                    //                   m2=(ntile 2np+1, k-lo), m3=(ntile 2np+1, k-hi)
                    int row = lw * 32 + np * 16 + ((lane >> 4) << 3) + (lane & 7);
                    uint32_t off = SWZ128((uint32_t)(row * 128 + ks * 32 + ((lane >> 3) & 1) * 16));
                    uint32_t r[4];
                    ldsm4(r, bHI + off);
                    bh[np * 2][0]     = r[0]; bh[np * 2][1]     = r[1];
                    bh[np * 2 + 1][0] = r[2]; bh[np * 2 + 1][1] = r[3];
                    ldsm4(r, bLO + off);
                    bl[np * 2][0]     = r[0]; bl[np * 2][1]     = r[1];
                    bl[np * 2 + 1][0] = r[2]; bl[np * 2 + 1][1] = r[3];
                }
                #pragma unroll
                for (int ot = 0; ot < 4; ot++) {
                    int row = ow * 64 + ot * 16 + (lane & 15);
                    uint32_t off = SWZ128((uint32_t)(row * 128 + ks * 32 + (lane >> 4) * 16));
                    uint32_t ah[4], al[4];
                    ldsm4(ah, aHI + off);
                    ldsm4(al, aLO + off);
                    #pragma unroll
                    for (int nt = 0; nt < 4; nt++) {
                        mma16816(c[ot][nt], ah, bh[nt]);
                        mma16816(c[ot][nt], ah, bl[nt]);
                        mma16816(c[ot][nt], al, bh[nt]);
                    }
                }
            }
            __syncthreads();
        }
    }

    // ---- epilogue: bias + store ----
    int og0 = oh * 128 + ow * 64;
    #pragma unroll
    for (int ot = 0; ot < 4; ot++) {
        #pragma unroll
        for (int r2 = 0; r2 < 2; r2++) {
            int o = og0 + ot * 16 + (lane >> 2) + r2 * 8;
            float bj = bias[o];
            float* orow = out + ((size_t)(b * COUT + o)) * LEN + l0;
            #pragma unroll
            for (int nt = 0; nt < 4; nt++) {
                int lc = lw * 32 + nt * 8 + (lane & 3) * 2;
                *(float2*)(orow + lc) =
                    make_float2(c[ot][nt][r2 * 2] + bj, c[ot][nt][r2 * 2 + 1] + bj);
            }
        }
    }
}

// ---------------- launch ----------------
extern "C" void kernel_launch(void* const* d_in, const int* in_sizes, int n_in,
                              void* d_out, int out_size)
{
    const float* x        = (const float*)d_in[0];
    const float* weight   = (const float*)d_in[1];
    const float* bias     = (const float*)d_in[2];
    const float* offset_w = (const float*)d_in[3];
    const float* offset_b = (const float*)d_in[4];
    float* out = (float*)d_out;

    const int smem_off  = (256 * 136 + 7 * 256 * 8) * 4;   // 196608
    const int smem_main = 65536;

    cudaFuncSetAttribute(offsets_kernel, cudaFuncAttributeMaxDynamicSharedMemorySize, smem_off);
    cudaFuncSetAttribute(main_kernel,    cudaFuncAttributeMaxDynamicSharedMemorySize, smem_main);

    wprep_kernel<<<(KK * NCHUNK * 2 * 2 * 8192 + 255) / 256, 256>>>(weight);
    offsets_kernel<<<dim3(LEN / TLO, BATCH), 256, smem_off>>>(x, offset_w, offset_b);
    main_kernel<<<dim3(LEN / NT, 2, BATCH), 256, smem_main>>>(x, bias, out);
}

// round 7
// speedup vs baseline: 1.2146x; 1.2146x over previous
#include <cuda_runtime.h>
#include <cuda_bf16.h>
#include <cstdint>

#define CIN   256
#define COUT  256
#define LEN   8192
#define KK    7
#define BATCH 4
#define NT    128    // l-tile of main kernel
#define TLO   128    // l-tile of offsets kernel
#define NCHUNK 4     // i-chunks of 64 per k

// ---------------- device scratch ----------------
__device__ int2          g_tidx[BATCH * KK * LEN];   // (x0c, x1c)
__device__ float2        g_tw[BATCH * KK * LEN];     // (wa, wb)
// weight tiles: t = ((k*4+ic)*2+oh)*2+plane, each [128 o][64 i] bf16, SW128 pre-swizzled
__device__ __nv_bfloat16 g_wA[KK * NCHUNK * 2 * 2 * 8192];

#define SWZ128(x)  ((x) ^ (((x) >> 3) & 0x70))
#define SLOT_BYTES 65536

// ---------------- PTX helpers (portable, sm_80-era) ----------------
__device__ __forceinline__ uint32_t smem_u32(const void* p) {
    uint32_t a;
    asm("{ .reg .u64 t; cvta.to.shared.u64 t, %1; cvt.u32.u64 %0, t; }" : "=r"(a) : "l"(p));
    return a;
}
__device__ __forceinline__ void cp16(uint32_t dst, const void* src) {
    asm volatile("cp.async.cg.shared.global [%0], [%1], 16;" :: "r"(dst), "l"(src));
}
__device__ __forceinline__ void ldsm4(uint32_t* r, uint32_t addr) {
    asm volatile("ldmatrix.sync.aligned.m8n8.x4.shared.b16 {%0,%1,%2,%3}, [%4];"
        : "=r"(r[0]), "=r"(r[1]), "=r"(r[2]), "=r"(r[3]) : "r"(addr));
}
__device__ __forceinline__ void mma16816(float* c, const uint32_t* a, const uint32_t* b) {
    asm volatile("mma.sync.aligned.m16n8k16.row.col.f32.bf16.bf16.f32 "
        "{%0,%1,%2,%3}, {%4,%5,%6,%7}, {%8,%9}, {%0,%1,%2,%3};"
        : "+f"(c[0]), "+f"(c[1]), "+f"(c[2]), "+f"(c[3])
        : "r"(a[0]), "r"(a[1]), "r"(a[2]), "r"(a[3]), "r"(b[0]), "r"(b[1]));
}
#define BAR_SYNC(id)   asm volatile("bar.sync %0, %1;"   :: "r"(id), "r"(384) : "memory")
#define BAR_ARRIVE(id) asm volatile("bar.arrive %0, %1;" :: "r"(id), "r"(384) : "memory")

// ---------- kernel 1: weight split + pre-swizzle ----------
__global__ void wprep_kernel(const float* __restrict__ w) {
    int e = blockIdx.x * 256 + threadIdx.x;
    if (e >= KK * NCHUNK * 2 * 2 * 8192) return;
    int t  = e >> 13;
    int r  = e & 8191;
    int o  = r >> 6;
    int i  = r & 63;
    int plane = t & 1;
    int oh    = (t >> 1) & 1;
    int ic    = (t >> 2) & 3;
    int k     = t >> 4;
    float v = w[((oh * 128 + o) * CIN + ic * 64 + i) * KK + k];
    __nv_bfloat16 hi  = __float2bfloat16(v);
    __nv_bfloat16 val = plane ? __float2bfloat16(v - __bfloat162float(hi)) : hi;
    uint32_t swz = SWZ128((uint32_t)(o * 128 + i * 2));
    g_wA[t * 8192 + (swz >> 1)] = val;
}

// ---------- kernel 2: offset conv + interpolation tables ----------
__global__ __launch_bounds__(256, 1) void offsets_kernel(
    const float* __restrict__ x,
    const float* __restrict__ ow,
    const float* __restrict__ ob)
{
    extern __shared__ float sm[];
    float* xs  = sm;              // 256 * 136
    float* ows = sm + 256 * 136;  // 7 * 256 * 8

    int tid = threadIdx.x;
    int b   = blockIdx.y;
    int l0  = blockIdx.x * TLO;
    const float* xb = x + (size_t)b * CIN * LEN;

    for (int idx = tid; idx < 256 * 134; idx += 256) {
        int i = idx / 134;
        int c = idx - i * 134;
        int g = l0 - 3 + c;
        xs[i * 136 + c] = (g >= 0 && g < LEN) ? xb[i * LEN + g] : 0.0f;
    }
    for (int e = tid; e < KK * CIN * KK; e += 256) {
        int r  = e / 7;
        int kk = e - r * 7;
        ows[r * 8 + kk] = ow[e];
    }
    __syncthreads();

    int w    = tid >> 5;
    int lane = tid & 31;
    if (w < 7) {
        int k = w;
        float a0 = 0.f, a1 = 0.f, a2 = 0.f, a3 = 0.f;
        const float* xrow0 = xs + 4 * lane;
        const float* wrow  = ows + k * 256 * 8;
        #pragma unroll 4
        for (int i = 0; i < 256; i++) {
            const float4* xr = (const float4*)(xrow0 + i * 136);
            float4 A = xr[0], B4 = xr[1], C4 = xr[2];
            float xw[12] = {A.x, A.y, A.z, A.w, B4.x, B4.y, B4.z, B4.w,
                            C4.x, C4.y, C4.z, C4.w};
            const float4* wr = (const float4*)(wrow + i * 8);
            float4 W0 = wr[0], W1 = wr[1];
            float wv[7] = {W0.x, W0.y, W0.z, W0.w, W1.x, W1.y, W1.z};
            #pragma unroll
            for (int kk = 0; kk < 7; kk++) {
                a0 += wv[kk] * xw[0 + kk];
                a1 += wv[kk] * xw[1 + kk];
                a2 += wv[kk] * xw[2 + kk];
                a3 += wv[kk] * xw[3 + kk];
            }
        }
        float bk = ob[k];
        float accs[4] = {a0, a1, a2, a3};
        #pragma unroll
        for (int d = 0; d < 4; d++) {
            int lg = l0 + 4 * lane + d;
            float loc = (float)(lg + k) + accs[d] + bk;
            int ix0 = (int)floorf(loc);
            int i0c = min(max(ix0, 0), LEN - 1);
            int i1c = min(max(ix0 + 1, 0), LEN - 1);
            int o = (b * 7 + k) * LEN + lg;
            g_tidx[o] = make_int2(i0c, i1c);
            g_tw[o]   = make_float2((float)i1c - loc, loc - (float)i0c);
        }
    }
}

// ---------- kernel 3: warp-specialized GEMM (bf16 split x3) ----------
// 384 threads: warps 0-7 consumers (mma), warps 8-11 producers (A cp.async + B gather).
// 2-slot smem ring; per slot: A_hi@0, A_lo@16K, B_hi@32K, B_lo@48K (64KB).
// Named barriers: full[s]=1+s (prod arrive, cons sync), empty[s]=3+s (cons arrive, prod sync).
__global__ __launch_bounds__(384, 1) void main_kernel(
    const float* __restrict__ x,
    const float* __restrict__ bias,
    float* __restrict__ out)
{
    extern __shared__ char smem[];
    uint32_t sb = smem_u32(smem);

    int tid = threadIdx.x;
    int l0  = blockIdx.x * NT;
    int oh  = blockIdx.y;
    int b   = blockIdx.z;
    const float* xb = x + (size_t)b * CIN * LEN;

    if (tid < 256) {
        // ================= consumers =================
        int wid  = tid >> 5;
        int lane = tid & 31;
        int ow   = wid >> 2;     // 0..1 -> 64-o subtile
        int lw   = wid & 3;      // 0..3 -> 32-l subtile

        float c[4][4][4];
        #pragma unroll
        for (int ot = 0; ot < 4; ot++)
            #pragma unroll
            for (int nt = 0; nt < 4; nt++)
                #pragma unroll
                for (int r = 0; r < 4; r++) c[ot][nt][r] = 0.f;

        for (int cc = 0; cc < KK * NCHUNK; cc++) {
            int slot = cc & 1;
            BAR_SYNC(1 + slot);                    // wait full
            uint32_t aHI = sb + slot * SLOT_BYTES;
            uint32_t aLO = aHI + 16384;
            uint32_t bHI = aHI + 32768;
            uint32_t bLO = aHI + 49152;

            #pragma unroll
            for (int ks = 0; ks < 4; ks++) {
                uint32_t bh[4][2], bl[4][2];
                #pragma unroll
                for (int np = 0; np < 2; np++) {
                    int row = lw * 32 + np * 16 + ((lane >> 4) << 3) + (lane & 7);
                    uint32_t off = SWZ128((uint32_t)(row * 128 + ks * 32 + ((lane >> 3) & 1) * 16));
                    uint32_t r[4];
                    ldsm4(r, bHI + off);
                    bh[np * 2][0]     = r[0]; bh[np * 2][1]     = r[1];
                    bh[np * 2 + 1][0] = r[2]; bh[np * 2 + 1][1] = r[3];
                    ldsm4(r, bLO + off);
                    bl[np * 2][0]     = r[0]; bl[np * 2][1]     = r[1];
                    bl[np * 2 + 1][0] = r[2]; bl[np * 2 + 1][1] = r[3];
                }
                #pragma unroll
                for (int ot = 0; ot < 4; ot++) {
                    int row = ow * 64 + ot * 16 + (lane & 15);
                    uint32_t off = SWZ128((uint32_t)(row * 128 + ks * 32 + (lane >> 4) * 16));
                    uint32_t ah[4], al[4];
                    ldsm4(ah, aHI + off);
                    ldsm4(al, aLO + off);
                    #pragma unroll
                    for (int nt = 0; nt < 4; nt++) {
                        mma16816(c[ot][nt], ah, bh[nt]);
                        mma16816(c[ot][nt], ah, bl[nt]);
                        mma16816(c[ot][nt], al, bh[nt]);
                    }
                }
            }
            if (cc < KK * NCHUNK - 2) BAR_ARRIVE(3 + slot);   // signal empty
        }

        // ---- epilogue: bias + store ----
        int og0 = oh * 128 + ow * 64;
        #pragma unroll
        for (int ot = 0; ot < 4; ot++) {
            #pragma unroll
            for (int r2 = 0; r2 < 2; r2++) {
                int o = og0 + ot * 16 + (lane >> 2) + r2 * 8;
                float bj = bias[o];
                float* orow = out + ((size_t)(b * COUT + o)) * LEN + l0;
                #pragma unroll
                for (int nt = 0; nt < 4; nt++) {
                    int lc = lw * 32 + nt * 8 + (lane & 3) * 2;
                    *(float2*)(orow + lc) =
                        make_float2(c[ot][nt][r2 * 2] + bj, c[ot][nt][r2 * 2 + 1] + bj);
                }
            }
        }
    } else {
        // ================= producers =================
        int ptid = tid - 256;      // 0..127, one l-row each

        for (int cc = 0; cc < KK * NCHUNK; cc++) {
            int k    = cc >> 2;    // k outer, ic inner (R4 proven order)
            int ic   = cc & 3;
            int slot = cc & 1;
            if (cc >= 2) BAR_SYNC(3 + slot);       // wait empty

            // ---- A tiles (hi+lo, 32KB contiguous) via cp.async ----
            uint32_t aBase = sb + slot * SLOT_BYTES;
            int tb = ((k * NCHUNK + ic) * 2 + oh) * 2;
            const char* srcA = (const char*)(g_wA + (size_t)tb * 8192);
            #pragma unroll
            for (int q = 0; q < 16; q++)
                cp16(aBase + q * 2048 + ptid * 16, srcA + q * 2048 + ptid * 16);
            asm volatile("cp.async.commit_group;" ::: "memory");

            // ---- B tile: gather + interp + hi/lo split -> SW128 smem ----
            int tix = (b * 7 + k) * LEN + l0 + ptid;
            int2   ii = g_tidx[tix];
            float2 wv = g_tw[tix];
            const float* p0 = xb + ii.x;
            const float* p1 = xb + ii.y;
            char* bH = smem + slot * SLOT_BYTES + 32768;
            char* bL = smem + slot * SLOT_BYTES + 49152;

            #pragma unroll
            for (int g = 0; g < 8; g++) {
                uint32_t hp[4], lp[4];
                #pragma unroll
                for (int j = 0; j < 4; j++) {
                    size_t i0 = (size_t)(ic * 64 + g * 8 + j * 2) * LEN;
                    float v0 = wv.x * p0[i0]       + wv.y * p1[i0];
                    float v1 = wv.x * p0[i0 + LEN] + wv.y * p1[i0 + LEN];
                    __nv_bfloat16 h0 = __float2bfloat16(v0);
                    __nv_bfloat16 h1 = __float2bfloat16(v1);
                    __nv_bfloat16 e0 = __float2bfloat16(v0 - __bfloat162float(h0));
                    __nv_bfloat16 e1 = __float2bfloat16(v1 - __bfloat162float(h1));
                    __nv_bfloat162 hh(h0, h1), ll(e0, e1);
                    hp[j] = *(uint32_t*)&hh;
                    lp[j] = *(uint32_t*)&ll;
                }
                uint32_t so = SWZ128((uint32_t)(ptid * 128 + g * 16));
                *(uint4*)(bH + so) = make_uint4(hp[0], hp[1], hp[2], hp[3]);
                *(uint4*)(bL + so) = make_uint4(lp[0], lp[1], lp[2], lp[3]);
            }
            asm volatile("cp.async.wait_group 0;" ::: "memory");
            __threadfence_block();
            BAR_ARRIVE(1 + slot);                  // signal full
        }
    }
}

// ---------------- launch ----------------
extern "C" void kernel_launch(void* const* d_in, const int* in_sizes, int n_in,
                              void* d_out, int out_size)
{
    const float* x        = (const float*)d_in[0];
    const float* weight   = (const float*)d_in[1];
    const float* bias     = (const float*)d_in[2];
    const float* offset_w = (const float*)d_in[3];
    const float* offset_b = (const float*)d_in[4];
    float* out = (float*)d_out;

    const int smem_off  = (256 * 136 + 7 * 256 * 8) * 4;   // 196608
    const int smem_main = 2 * SLOT_BYTES;                  // 131072

    cudaFuncSetAttribute(offsets_kernel, cudaFuncAttributeMaxDynamicSharedMemorySize, smem_off);
    cudaFuncSetAttribute(main_kernel,    cudaFuncAttributeMaxDynamicSharedMemorySize, smem_main);

    wprep_kernel<<<(KK * NCHUNK * 2 * 2 * 8192 + 255) / 256, 256>>>(weight);
    offsets_kernel<<<dim3(LEN / TLO, BATCH), 256, smem_off>>>(x, offset_w, offset_b);
    main_kernel<<<dim3(LEN / NT, 2, BATCH), 384, smem_main>>>(x, bias, out);
}